// round 9
// baseline (speedup 1.0000x reference)
#include <cuda_runtime.h>
#include <cstdint>

#define TSTEPS  1024
#define FEAT    64
#define UNITS   256
#define FOURU   1024
#define KQ      64        // K rows per k-quarter
#define NCOLS   128       // gate-columns per CTA: 32 units x 4 gates
#define CLUSTER 8
#define RTHREADS 512
#define BB      32        // batch rows per cluster
#define GB      16        // batches per group (2 groups)
#define NCLUST  16
#define HBUF_F  (UNITS * GB + 4 * 4)   // 4112 floats per h buffer (skew 4/64rows)
#define SLAB_F  (32 * GB)              // 512 floats = 2048 B
#define EXPECT_BYTES (CLUSTER * SLAB_F * 4)   // 16384 B per group-phase

// z_x scratch: zx[t][b][c], c = unit*4 + gate, bias folded in. Two 1 GB halves.
__device__ float g_zxA[(size_t)512 * 512 * 1024];
__device__ float g_zxB[(size_t)512 * 512 * 1024];

// ---------- packed f32x2 helpers ----------
__device__ __forceinline__ unsigned long long dup2(float x) {
    unsigned long long r; uint32_t u = __float_as_uint(x);
    asm("mov.b64 %0, {%1, %1};" : "=l"(r) : "r"(u));
    return r;
}
__device__ __forceinline__ void fma2(unsigned long long& d,
                                     unsigned long long a,
                                     unsigned long long b) {
    asm("fma.rn.f32x2 %0, %1, %2, %0;" : "+l"(d) : "l"(a), "l"(b));
}
__device__ __forceinline__ float2 up2(unsigned long long v) {
    float2 r;
    asm("mov.b64 {%0, %1}, %2;" : "=f"(r.x), "=f"(r.y) : "l"(v));
    return r;
}
__device__ __forceinline__ unsigned long long xadd(unsigned long long v, int m) {
    uint32_t lo, hi;
    asm("mov.b64 {%0,%1}, %2;" : "=r"(lo), "=r"(hi) : "l"(v));
    lo = __shfl_xor_sync(0xffffffffu, lo, m);
    hi = __shfl_xor_sync(0xffffffffu, hi, m);
    unsigned long long o;
    asm("mov.b64 %0, {%1,%2};" : "=l"(o) : "r"(lo), "r"(hi));
    asm("add.rn.f32x2 %0, %0, %1;" : "+l"(v) : "l"(o));
    return v;
}
__device__ __forceinline__ float fsig(float x) {
    return __fdividef(1.0f, 1.0f + __expf(-x));
}
__device__ __forceinline__ float ftanh(float x) {
    return fmaf(2.0f, fsig(2.0f * x), -1.0f);
}
__device__ __forceinline__ void mbar_wait(uint32_t mbar, uint32_t parity) {
    uint32_t done;
    do {
        asm volatile(
            "{\n\t.reg .pred P;\n\t"
            "mbarrier.try_wait.parity.acquire.cluster.shared::cta.b64 P, [%1], %2, 0x989680;\n\t"
            "selp.b32 %0, 1, 0, P;\n\t}"
            : "=r"(done) : "r"(mbar), "r"(parity) : "memory");
    } while (!done);
}

// ============================================================================
// Kernel 1: zx = x @ W(perm) + bias(perm). Classic 128x128 fp32 tile GEMM.
// grid (8 col-tiles, 8 t-tiles, 512 batches), 256 thr, thread tile 8t x 8c.
// ============================================================================
__global__ void __launch_bounds__(256)
zx_kernel(const float* __restrict__ x, const float* __restrict__ W,
          const float* __restrict__ bias)
{
    __shared__ float ws[64 * 132];
    __shared__ float xs[64 * 132];

    const int tid = threadIdx.x;
    const int cb  = blockIdx.x;     // 128-col tile (0..7), fastest: L2 reuse of x
    const int tb  = blockIdx.y;     // 128-t tile  (0..7)
    const int b   = blockIdx.z;     // batch       (0..511)

    // stage W tile (permuted cols): ws[k][cc]
    for (int idx = tid; idx < 64 * 128; idx += 256) {
        const int k = idx >> 7, cc = idx & 127;
        const int c = cb * 128 + cc;
        ws[k * 132 + cc] = W[(size_t)k * FOURU + (c & 3) * UNITS + (c >> 2)];
    }
    // stage x tile transposed: xs[k][tt]
    {
        const float* xb = x + ((size_t)b * TSTEPS + tb * 128) * FEAT;
        for (int idx = tid; idx < 128 * 16; idx += 256) {
            const int tt = idx >> 4, k4 = idx & 15;
            const float4 v = *(const float4*)(xb + (size_t)tt * FEAT + k4 * 4);
            xs[(k4 * 4 + 0) * 132 + tt] = v.x;
            xs[(k4 * 4 + 1) * 132 + tt] = v.y;
            xs[(k4 * 4 + 2) * 132 + tt] = v.z;
            xs[(k4 * 4 + 3) * 132 + tt] = v.w;
        }
    }
    __syncthreads();

    const int tx = tid & 15;    // col-oct (8 cols)
    const int ty = tid >> 4;    // t-oct  (8 rows)

    unsigned long long acc[8][4];
    #pragma unroll
    for (int j = 0; j < 4; j++) {
        const int c0 = cb * 128 + tx * 8 + 2 * j * 2;  // careful: pairs (2j,2j+1)
        (void)c0;
    }
    // init accumulators with bias pairs
    {
        unsigned long long bp[4];
        #pragma unroll
        for (int j = 0; j < 4; j++) {
            const int ca = cb * 128 + tx * 8 + 2 * j;
            const int cbn = ca + 1;
            uint32_t lo = __float_as_uint(bias[(ca  & 3) * UNITS + (ca  >> 2)]);
            uint32_t hi = __float_as_uint(bias[(cbn & 3) * UNITS + (cbn >> 2)]);
            unsigned long long r;
            asm("mov.b64 %0, {%1,%2};" : "=l"(r) : "r"(lo), "r"(hi));
            bp[j] = r;
        }
        #pragma unroll
        for (int i = 0; i < 8; i++)
            #pragma unroll
            for (int j = 0; j < 4; j++) acc[i][j] = bp[j];
    }

    #pragma unroll 4
    for (int k = 0; k < 64; k++) {
        const float4 a0 = *(const float4*)(xs + k * 132 + ty * 8);
        const float4 a1 = *(const float4*)(xs + k * 132 + ty * 8 + 4);
        const ulonglong2 w0 = *(const ulonglong2*)(ws + k * 132 + tx * 8);
        const ulonglong2 w1 = *(const ulonglong2*)(ws + k * 132 + tx * 8 + 4);
        const unsigned long long wv[4] = { w0.x, w0.y, w1.x, w1.y };
        const unsigned long long ad[8] = { dup2(a0.x), dup2(a0.y), dup2(a0.z), dup2(a0.w),
                                           dup2(a1.x), dup2(a1.y), dup2(a1.z), dup2(a1.w) };
        #pragma unroll
        for (int i = 0; i < 8; i++)
            #pragma unroll
            for (int j = 0; j < 4; j++)
                fma2(acc[i][j], ad[i], wv[j]);
    }

    #pragma unroll
    for (int i = 0; i < 8; i++) {
        const int t = tb * 128 + ty * 8 + i;
        float* o = ((t < 512) ? g_zxA : g_zxB) +
                   ((size_t)(t & 511) * 512 + b) * FOURU + cb * 128 + tx * 8;
        const float2 p0 = up2(acc[i][0]), p1 = up2(acc[i][1]);
        const float2 p2 = up2(acc[i][2]), p3 = up2(acc[i][3]);
        *(float4*)(o)     = make_float4(p0.x, p0.y, p1.x, p1.y);
        *(float4*)(o + 4) = make_float4(p2.x, p2.y, p3.x, p3.y);
    }
}

// ============================================================================
// Kernel 2: recurrent LSTM, two-group pipelined. 16 clusters x 8 CTAs x 512.
// Groups A (batch 0-15) and B (16-31) are independent recurrences; B's GEMM
// hides A's h-exchange (DSMEM bulk) and vice versa. Warp = 2 units; lane =
// (kq, batch-quad, unit-half). Thread GEMM tile: 4 batches x 4 gates over its
// K-quarter; butterfly-reduce; gates for 1 batch. Epilogue: softmax over
// size-1 axis == 1, so out[b,:] = sigmoid(h_T[b].dw + db).
// ============================================================================
extern "C" __global__ void __launch_bounds__(RTHREADS, 1) __cluster_dims__(CLUSTER, 1, 1)
lstm_kernel(const float* __restrict__ Uh, const float* __restrict__ dw,
            const float* __restrict__ db, float* __restrict__ out)
{
    extern __shared__ float smem[];
    float* Uc   = smem;                              // [256][128] 131072 B
    float* hb   = smem + UNITS * NCOLS;              // [2g][2buf][HBUF_F]
    float* slab = hb + 4 * HBUF_F;                   // [2g][2ph][SLAB_F]

    const int tid = threadIdx.x;
    uint32_t rank, cid;
    asm("mov.u32 %0, %%cluster_ctarank;" : "=r"(rank));
    asm("mov.u32 %0, %%clusterid.x;"     : "=r"(cid));

    uint32_t smem_u32;
    asm("{ .reg .u64 t0; cvta.to.shared.u64 t0, %1; cvt.u32.u64 %0, t0; }"
        : "=r"(smem_u32) : "l"(smem));
    const uint32_t hb_u32    = smem_u32 + UNITS * NCOLS * 4;
    const uint32_t slab_u32  = hb_u32 + 4 * HBUF_F * 4;
    const uint32_t inbox_u32 = slab_u32 + 4 * SLAB_F * 4;   // 4 mbarriers

    for (int idx = tid; idx < UNITS * NCOLS; idx += RTHREADS) {
        const int k = idx >> 7, c = idx & 127;
        Uc[idx] = Uh[(size_t)k * FOURU + (c & 3) * UNITS + (int)rank * 32 + (c >> 2)];
    }
    for (int i = tid; i < 4 * HBUF_F; i += RTHREADS) hb[i] = 0.0f;
    if (tid == 0) {
        #pragma unroll
        for (int m = 0; m < 4; m++)
            asm volatile("mbarrier.init.shared.b64 [%0], 1;"
                         :: "r"(inbox_u32 + m * 8) : "memory");
    }
    __syncthreads();
    asm volatile("barrier.cluster.arrive.aligned;" ::: "memory");
    asm volatile("barrier.cluster.wait.aligned;"   ::: "memory");

    const int wid  = tid >> 5, lane = tid & 31;
    const int kq   = lane >> 3;          // K quarter
    const int bq2  = (lane >> 1) & 3;    // batch quad (4 batches)
    const int u1   = lane & 1;           // unit half
    const int unit = wid * 2 + u1;       // local unit 0..31
    const int bg   = bq2 * 4 + kq;       // my gate batch within group (0..15)
    const int cb   = ((int)rank * 32 + unit) * 4;   // zx column base

    // weight / act pointers
    const float* ucp  = Uc + (kq * KQ) * NCOLS + unit * 4;
    const int act_off = (kq * KQ) * GB + kq * 4 + bq2 * 4;   // +skew 4/64rows

    float cstA = 0.0f, cstB = 0.0f;

    // preload zx(t=0) for my batch in each group
    const int bA = (int)cid * BB + bg;
    const int bBt = bA + GB;
    float4 zcA = *(const float4*)(g_zxA + (size_t)bA  * FOURU + cb);
    float4 zcB = *(const float4*)(g_zxA + (size_t)bBt * FOURU + cb);

    for (int t = 0; t < TSTEPS; t++) {
        const int bufc = t & 1, bufn = (t + 1) & 1;

        // prefetch zx(t+1)
        float4 znA = zcA, znB = zcB;
        if (t < TSTEPS - 1) {
            const float* zp = ((t + 1 < 512) ? g_zxA : g_zxB) +
                              ((size_t)((t + 1) & 511) * 512) * FOURU;
            znA = *(const float4*)(zp + (size_t)bA  * FOURU + cb);
            znB = *(const float4*)(zp + (size_t)bBt * FOURU + cb);
        }

        #pragma unroll
        for (int g = 0; g < 2; g++) {
            // wait this group's h(t), then arm next phase
            if (t > 0)
                mbar_wait(inbox_u32 + (uint32_t)((g * 2 + bufc) * 8),
                          (uint32_t)(((t - 1) >> 1) & 1));
            if (tid == 0)
                asm volatile("mbarrier.arrive.expect_tx.shared.b64 _, [%0], %1;"
                    :: "r"(inbox_u32 + (uint32_t)((g * 2 + bufn) * 8)),
                       "r"((uint32_t)EXPECT_BYTES) : "memory");

            // ---- GEMM over my K-quarter: 2 batch-pairs x 4 gates ----
            unsigned long long acc[2][4];
            #pragma unroll
            for (int p = 0; p < 2; p++)
                #pragma unroll
                for (int gg = 0; gg < 4; gg++) acc[p][gg] = 0ull;

            const float* ap = hb + (g * 2 + bufc) * HBUF_F + act_off;
            #pragma unroll 4
            for (int kk = 0; kk < KQ; kk++) {
                const float4 u4 = *(const float4*)(ucp + kk * NCOLS);
                const unsigned long long ug[4] = { dup2(u4.x), dup2(u4.y),
                                                   dup2(u4.z), dup2(u4.w) };
                const ulonglong2 a = *(const ulonglong2*)(ap + kk * GB);
                #pragma unroll
                for (int gg = 0; gg < 4; gg++) {
                    fma2(acc[0][gg], a.x, ug[gg]);
                    fma2(acc[1][gg], a.y, ug[gg]);
                }
            }

            // butterfly across kq lanes
            #pragma unroll
            for (int p = 0; p < 2; p++)
                #pragma unroll
                for (int gg = 0; gg < 4; gg++) {
                    acc[p][gg] = xadd(acc[p][gg], 8);
                    acc[p][gg] = xadd(acc[p][gg], 16);
                }

            // my batch within quad = kq: pair kq>>1, elem kq&1
            float zi, zf, zg, zo;
            {
                const unsigned long long s0 = (kq & 2) ? acc[1][0] : acc[0][0];
                const unsigned long long s1 = (kq & 2) ? acc[1][1] : acc[0][1];
                const unsigned long long s2 = (kq & 2) ? acc[1][2] : acc[0][2];
                const unsigned long long s3 = (kq & 2) ? acc[1][3] : acc[0][3];
                const float2 p0 = up2(s0), p1 = up2(s1), p2 = up2(s2), p3 = up2(s3);
                zi = (kq & 1) ? p0.y : p0.x;
                zf = (kq & 1) ? p1.y : p1.x;
                zg = (kq & 1) ? p2.y : p2.x;
                zo = (kq & 1) ? p3.y : p3.x;
            }

            // gates (zx includes x@W + bias)
            const float4 zc = g ? zcB : zcA;
            float& cst = g ? cstB : cstA;
            const float ig = fsig(zi + zc.x), fg = fsig(zf + zc.y);
            const float gg2 = ftanh(zg + zc.z), og = fsig(zo + zc.w);
            cst = fmaf(fg, cst, ig * gg2);
            const float hv = og * ftanh(cst);

            // stage into slab[g][bufn], sync, 8 bulk sends (overlaps next group)
            slab[(g * 2 + bufn) * SLAB_F + unit * GB + bg] = hv;
            __syncthreads();
            if (tid == 0) {
                asm volatile("fence.proxy.async.shared::cta;" ::: "memory");
                const uint32_t src = slab_u32 + (uint32_t)((g * 2 + bufn) * SLAB_F * 4);
                const uint32_t dstl = hb_u32 + (uint32_t)((g * 2 + bufn) * HBUF_F * 4
                                     + 2048 * rank + (rank >> 1) * 16);
                const uint32_t mbl = inbox_u32 + (uint32_t)((g * 2 + bufn) * 8);
                #pragma unroll
                for (int r = 0; r < CLUSTER; r++) {
                    uint32_t dsta, mba;
                    asm("mapa.shared::cluster.u32 %0, %1, %2;" : "=r"(dsta) : "r"(dstl), "r"(r));
                    asm("mapa.shared::cluster.u32 %0, %1, %2;" : "=r"(mba)  : "r"(mbl),  "r"(r));
                    asm volatile(
                        "cp.async.bulk.shared::cluster.shared::cta.mbarrier::complete_tx::bytes "
                        "[%0], [%1], %2, [%3];"
                        :: "r"(dsta), "r"(src), "r"((uint32_t)(SLAB_F * 4)), "r"(mba)
                        : "memory");
                }
            }
        }
        zcA = znA; zcB = znB;
    }

    // final h_T in buf0 of each group
    mbar_wait(inbox_u32 + 0 * 8, 1u);
    mbar_wait(inbox_u32 + 2 * 8, 1u);

    // ---- epilogue: out[b, t] = sigmoid(h_T[b].dw + db) for all t ----
    {
        #pragma unroll
        for (int g = 0; g < 2; g++) {
            const float* hT = hb + (g * 2) * HBUF_F;
            float s = 0.0f;
            for (int u = lane; u < UNITS; u += 32)
                s += hT[u * GB + (u >> 6) * 4 + wid] * dw[u];
            #pragma unroll
            for (int o = 16; o > 0; o >>= 1)
                s += __shfl_xor_sync(0xffffffffu, s, o);
            const float val = fsig(s + db[0]);
            float* op = out + ((size_t)cid * BB + g * GB + wid) * TSTEPS;
            for (int i = lane; i < TSTEPS / 4; i += 32)
                *(float4*)(op + i * 4) = make_float4(val, val, val, val);
        }
    }
    asm volatile("barrier.cluster.arrive.aligned;" ::: "memory");
    asm volatile("barrier.cluster.wait.aligned;"   ::: "memory");
}

extern "C" void kernel_launch(void* const* d_in, const int* in_sizes, int n_in,
                              void* d_out, int out_size)
{
    const float* x  = (const float*)d_in[0];
    const float* W  = (const float*)d_in[1];
    const float* Uh = (const float*)d_in[2];
    const float* b  = (const float*)d_in[3];
    const float* dw = (const float*)d_in[4];
    const float* db = (const float*)d_in[5];
    float* out = (float*)d_out;

    zx_kernel<<<dim3(8, 8, 512), 256>>>(x, W, b);

    const size_t rsm = (size_t)(UNITS * NCOLS + 4 * HBUF_F + 4 * SLAB_F) * sizeof(float) + 64;
    cudaFuncSetAttribute(lstm_kernel,
                         cudaFuncAttributeMaxDynamicSharedMemorySize, (int)rsm);
    lstm_kernel<<<NCLUST * CLUSTER, RTHREADS, rsm>>>(Uh, dw, db, out);
}